// round 1
// baseline (speedup 1.0000x reference)
#include <cuda_runtime.h>
#include <cuda_bf16.h>

#define T_STEPS 32768
#define H 1024
#define NB 64          // recurrence blocks (all resident: 64 <= 148 SMs)
#define RPB 16         // hidden rows per block
#define NT 256         // threads per recurrence block

// ---------------- device scratch (static, no allocations) ----------------
__device__ float g_c[(size_t)T_STEPS * H];   // precomputed x_t @ W_x^T + b  (128 MB)
__device__ float g_h[2][H];                  // double-buffered hidden state
__device__ int   g_flag[NB * 32];            // per-block progress flags, 128B apart

// ---------------- init: zero h0 and flags (graph-replay safe) ------------
__global__ void init_kernel() {
    int i = blockIdx.x * blockDim.x + threadIdx.x;
    if (i < H) g_h[0][i] = 0.f;
    if (i < NB) g_flag[i * 32] = 0;
}

// ---------------- GEMM: g_c[t][n] = sum_k x[t][k]*W_x[n][k] + b[n] -------
// classic 128x128x8 fp32 SGEMM, 256 threads, 8x8 microtiles
#define GBM 128
#define GBN 128
#define GBK 8

__global__ void __launch_bounds__(256) gemm_pre(const float* __restrict__ x,
                                                const float* __restrict__ W_i2h,
                                                const float* __restrict__ b_i2h) {
    __shared__ float As[GBK][GBM];
    __shared__ float Bs[GBK][GBN];
    int tid = threadIdx.x;
    int m0 = blockIdx.y * GBM;
    int n0 = blockIdx.x * GBN;
    int lr = tid >> 1;
    int lc = (tid & 1) * 4;
    const float* xg = x + (size_t)(m0 + lr) * 1024 + lc;
    const float* wg = W_i2h + (size_t)(n0 + lr) * 2048 + lc;  // W_x = cols [0,1024)
    int tx = tid & 15, ty = tid >> 4;

    float acc[8][8];
#pragma unroll
    for (int i = 0; i < 8; i++)
#pragma unroll
        for (int j = 0; j < 8; j++) acc[i][j] = 0.f;

    float4 a  = *(const float4*)xg;
    float4 bv = *(const float4*)wg;

    for (int k0 = 0; k0 < 1024; k0 += GBK) {
        __syncthreads();
        As[lc + 0][lr] = a.x;  As[lc + 1][lr] = a.y;
        As[lc + 2][lr] = a.z;  As[lc + 3][lr] = a.w;
        Bs[lc + 0][lr] = bv.x; Bs[lc + 1][lr] = bv.y;
        Bs[lc + 2][lr] = bv.z; Bs[lc + 3][lr] = bv.w;
        __syncthreads();
        if (k0 + GBK < 1024) {
            a  = *(const float4*)(xg + k0 + GBK);
            bv = *(const float4*)(wg + k0 + GBK);
        }
#pragma unroll
        for (int k = 0; k < GBK; k++) {
            float ar[8], br[8];
            *(float4*)(ar)     = *(const float4*)&As[k][ty * 8];
            *(float4*)(ar + 4) = *(const float4*)&As[k][ty * 8 + 4];
            *(float4*)(br)     = *(const float4*)&Bs[k][tx * 8];
            *(float4*)(br + 4) = *(const float4*)&Bs[k][tx * 8 + 4];
#pragma unroll
            for (int i = 0; i < 8; i++)
#pragma unroll
                for (int j = 0; j < 8; j++) acc[i][j] += ar[i] * br[j];
        }
    }

    float bias[8];
#pragma unroll
    for (int j = 0; j < 8; j++) bias[j] = __ldg(b_i2h + n0 + tx * 8 + j);
#pragma unroll
    for (int i = 0; i < 8; i++) {
        float4 v0 = make_float4(acc[i][0] + bias[0], acc[i][1] + bias[1],
                                acc[i][2] + bias[2], acc[i][3] + bias[3]);
        float4 v1 = make_float4(acc[i][4] + bias[4], acc[i][5] + bias[5],
                                acc[i][6] + bias[6], acc[i][7] + bias[7]);
        float* cp = g_c + (size_t)(m0 + ty * 8 + i) * 1024 + n0 + tx * 8;
        *(float4*)(cp)     = v0;
        *(float4*)(cp + 4) = v1;
    }
}

// ---------------- fast tanh: 1 - 2/(exp(2x)+1), inf-safe -----------------
__device__ __forceinline__ float tanh_fast(float x) {
    float e = __expf(2.f * x);          // +inf for large x -> result 1
    return 1.f - 2.f / (e + 1.f);       // e->0 for very negative x -> -1
}

// ---------------- recurrence: persistent, W_h in registers ---------------
// thread layout: rg = tid>>6 (4 row groups of 4 rows), kq = tid&63 (k chunk of 16)
__global__ void __launch_bounds__(NT) rnn_rec(const float* __restrict__ W_i2h) {
    __shared__ float sp[8][4];   // [warp][row-in-group] partials

    int tid = threadIdx.x;
    int b   = blockIdx.x;
    int r0  = b * RPB;
    int rg  = tid >> 6;          // 0..3
    int kq  = tid & 63;          // 0..63  (k = kq*16 .. kq*16+15)
    int warp = tid >> 5;
    int lane = tid & 31;

    // Load my W_h registers: rows r0+rg*4+r, k slice kq*16..+15
    float w[4][16];
#pragma unroll
    for (int r = 0; r < 4; r++) {
        const float* wp = W_i2h + (size_t)(r0 + rg * 4 + r) * 2048 + 1024 + kq * 16;
#pragma unroll
        for (int j4 = 0; j4 < 4; j4++) {
            float4 v = *(const float4*)(wp + j4 * 4);
            w[r][j4 * 4 + 0] = v.x; w[r][j4 * 4 + 1] = v.y;
            w[r][j4 * 4 + 2] = v.z; w[r][j4 * 4 + 3] = v.w;
        }
    }

    volatile int* flags = (volatile int*)g_flag;

    for (int t = 0; t < T_STEPS; t++) {
        // prefetch my c value (independent of barrier)
        float cval = 0.f;
        if (tid < RPB) cval = __ldg(g_c + (size_t)t * H + r0 + tid);

        // wait until every block has published h_t
        if (tid < NB) {
            while (flags[tid * 32] < t) {}
        }
        __syncthreads();
        __threadfence();   // acquire: order flag observation before h loads

        // load my h slice (bypass L1: written by other SMs last step)
        const float4* hp = (const float4*)(g_h[t & 1] + kq * 16);
        float4 h0 = __ldcg(hp + 0);
        float4 h1 = __ldcg(hp + 1);
        float4 h2 = __ldcg(hp + 2);
        float4 h3 = __ldcg(hp + 3);
        float hv[16] = {h0.x, h0.y, h0.z, h0.w, h1.x, h1.y, h1.z, h1.w,
                        h2.x, h2.y, h2.z, h2.w, h3.x, h3.y, h3.z, h3.w};

        float acc0 = 0.f, acc1 = 0.f, acc2 = 0.f, acc3 = 0.f;
#pragma unroll
        for (int j = 0; j < 16; j++) {
            float hj = hv[j];
            acc0 += w[0][j] * hj;
            acc1 += w[1][j] * hj;
            acc2 += w[2][j] * hj;
            acc3 += w[3][j] * hj;
        }
        // warp reduce (each warp covers 512 k's for its 4 rows)
#pragma unroll
        for (int off = 16; off > 0; off >>= 1) {
            acc0 += __shfl_down_sync(0xffffffffu, acc0, off);
            acc1 += __shfl_down_sync(0xffffffffu, acc1, off);
            acc2 += __shfl_down_sync(0xffffffffu, acc2, off);
            acc3 += __shfl_down_sync(0xffffffffu, acc3, off);
        }
        if (lane == 0) {
            sp[warp][0] = acc0; sp[warp][1] = acc1;
            sp[warp][2] = acc2; sp[warp][3] = acc3;
        }
        __syncthreads();

        if (tid < RPB) {
            int row = tid;          // 0..15
            int g   = row >> 2;     // row group
            int rr  = row & 3;
            float v = sp[g * 2][rr] + sp[g * 2 + 1][rr] + cval;
            float hn = tanh_fast(v);
            g_h[(t + 1) & 1][r0 + row] = hn;
            __threadfence();        // release my h writes before flag
        }
        __syncthreads();
        if (tid == 0) flags[b * 32] = t + 1;
    }
}

// ---------------- output: out[r] = h_T . W_h2o[r] + b_h2o[r] -------------
__global__ void __launch_bounds__(256) out_kernel(const float* __restrict__ W_h2o,
                                                  const float* __restrict__ b_h2o,
                                                  float* __restrict__ out) {
    int r = blockIdx.x * 8 + (threadIdx.x >> 5);
    int lane = threadIdx.x & 31;
    const float* wr = W_h2o + (size_t)r * 1024;
    const float* h  = g_h[T_STEPS & 1];
    float acc = 0.f;
    for (int k4 = lane; k4 < 256; k4 += 32) {
        float4 wv = *(const float4*)(wr + k4 * 4);
        float4 hv = *(const float4*)(h + k4 * 4);
        acc += wv.x * hv.x + wv.y * hv.y + wv.z * hv.z + wv.w * hv.w;
    }
#pragma unroll
    for (int off = 16; off > 0; off >>= 1)
        acc += __shfl_down_sync(0xffffffffu, acc, off);
    if (lane == 0) out[r] = acc + __ldg(b_h2o + r);
}

// ---------------- launch ----------------
extern "C" void kernel_launch(void* const* d_in, const int* in_sizes, int n_in,
                              void* d_out, int out_size) {
    const float* x      = (const float*)d_in[0];
    const float* W_i2h  = (const float*)d_in[1];
    const float* b_i2h  = (const float*)d_in[2];
    const float* W_h2o  = (const float*)d_in[3];
    const float* b_h2o  = (const float*)d_in[4];
    float* out = (float*)d_out;

    init_kernel<<<4, 256>>>();
    dim3 gg(1024 / GBN, T_STEPS / GBM);
    gemm_pre<<<gg, 256>>>(x, W_i2h, b_i2h);
    rnn_rec<<<NB, NT>>>(W_i2h);
    out_kernel<<<H / 8, 256>>>(W_h2o, b_h2o, out);
}